// round 2
// baseline (speedup 1.0000x reference)
#include <cuda_runtime.h>
#include <math.h>

#define B_    16
#define T_    128
#define V_    32000
#define H_    768
#define P_    384
#define NBOW_ 64
#define BT_   (B_ * T_)
#define EPS_  0.05f
#define TAU_  0.07f

// ---- scratch (no allocation allowed; __device__ globals) ----
__device__ float g_ce[BT_];
__device__ float g_vf[BT_];
__device__ float g_pooled[B_ * H_];
__device__ float g_h1[2 * B_ * P_];   // rows [0,16) = encoder branch, [16,32) = text branch
__device__ float g_z [2 * B_ * P_];   // l2-normalized projections

// ============================================================
// K1: per-token label-smoothed CE partials (online logsumexp)
// grid = BT_ blocks, 256 threads; each block scans 32000 floats
// ============================================================
__global__ void k_ce(const float* __restrict__ logits, const int* __restrict__ labels) {
    const int tok = blockIdx.x;
    const int tid = threadIdx.x;
    const float4* p = reinterpret_cast<const float4*>(logits + (size_t)tok * V_);

    float m = -1e30f, s = 0.0f, tsum = 0.0f;
    for (int i = tid; i < V_ / 4; i += 256) {
        float4 v = p[i];
        float xs[4] = {v.x, v.y, v.z, v.w};
        #pragma unroll
        for (int u = 0; u < 4; u++) {
            float x = xs[u];
            tsum += x;
            if (x > m) { s = s * __expf(m - x) + 1.0f; m = x; }
            else       { s += __expf(x - m); }
        }
    }

    __shared__ float shm[256], shs[256], sht[256];
    shm[tid] = m; shs[tid] = s; sht[tid] = tsum;
    __syncthreads();
    for (int off = 128; off > 0; off >>= 1) {
        if (tid < off) {
            float m2 = shm[tid + off], s2 = shs[tid + off];
            float M  = fmaxf(shm[tid], m2);
            shs[tid] = shs[tid] * __expf(shm[tid] - M) + s2 * __expf(m2 - M);
            shm[tid] = M;
            sht[tid] += sht[tid + off];
        }
        __syncthreads();
    }

    if (tid == 0) {
        float lse = shm[0] + logf(shs[0]);
        int lab = labels[tok];
        bool valid = (lab != 0) && (lab != -100);
        int lc = lab < 0 ? 0 : (lab >= V_ ? V_ - 1 : lab);
        float xl = logits[(size_t)tok * V_ + lc];
        float lp_lab = xl - lse;
        float lp_sum = sht[0] - (float)V_ * lse;
        float loss = -((1.0f - EPS_) * lp_lab + (EPS_ / (float)V_) * lp_sum);
        g_ce[tok] = valid ? loss : 0.0f;
        g_vf[tok] = valid ? 1.0f : 0.0f;
    }
}

// ============================================================
// K2: masked mean-pool of decoder_hidden over T  -> g_pooled
// grid = B_ blocks, 256 threads
// ============================================================
__global__ void k_pool(const float* __restrict__ dec, const int* __restrict__ mask) {
    const int b = blockIdx.x;
    __shared__ float msum;
    if (threadIdx.x == 0) {
        float acc = 0.0f;
        for (int t = 0; t < T_; t++) acc += (float)mask[b * T_ + t];
        msum = fmaxf(acc, 1.0f);
    }
    __syncthreads();
    for (int h = threadIdx.x; h < H_; h += blockDim.x) {
        float acc = 0.0f;
        for (int t = 0; t < T_; t++)
            acc += dec[((size_t)b * T_ + t) * H_ + h] * (float)mask[b * T_ + t];
        g_pooled[b * H_ + h] = acc / msum;
    }
}

// ---- correct 384-thread block reduction: fold 384->256, then pow2 tree ----
__device__ __forceinline__ float blockreduce384(float v, float* red, int tid) {
    red[tid] = v;
    __syncthreads();
    if (tid < 128) red[tid] += red[tid + 256];
    __syncthreads();
    for (int off = 128; off > 0; off >>= 1) {
        if (tid < off) red[tid] += red[tid + off];
        __syncthreads();
    }
    float r = red[0];
    __syncthreads();
    return r;
}

// ============================================================
// K3: LayerNorm + GEMV(H->P) + exact GELU, one block per row
// grid = 2*B_ blocks (first 16 = enc branch, next 16 = text), 384 threads
// ============================================================
__global__ void k_proj1(const float* __restrict__ enc,
                        const float* __restrict__ g_e, const float* __restrict__ be_,
                        const float* __restrict__ W1e, const float* __restrict__ b1e,
                        const float* __restrict__ g_t, const float* __restrict__ bt_,
                        const float* __restrict__ W1t, const float* __restrict__ b1t) {
    const int bid  = blockIdx.x;
    const bool is_e = bid < B_;
    const int row  = is_e ? bid : bid - B_;
    const float* x  = is_e ? (enc + row * H_) : (g_pooled + row * H_);
    const float* g  = is_e ? g_e : g_t;
    const float* bn = is_e ? be_ : bt_;
    const float* W1 = is_e ? W1e : W1t;
    const float* b1 = is_e ? b1e : b1t;
    float* out = g_h1 + bid * P_;

    __shared__ float ln[H_];
    __shared__ float red[P_];
    const int tid = threadIdx.x;

    float a0 = x[tid], a1 = x[tid + P_];
    float mean = blockreduce384(a0 + a1, red, tid) * (1.0f / (float)H_);

    float d0 = a0 - mean, d1 = a1 - mean;
    float var = blockreduce384(d0 * d0 + d1 * d1, red, tid) * (1.0f / (float)H_);
    float inv = rsqrtf(var + 1e-5f);

    ln[tid]       = d0 * inv * g[tid]       + bn[tid];
    ln[tid + P_]  = d1 * inv * g[tid + P_]  + bn[tid + P_];
    __syncthreads();

    float acc = b1[tid];
    #pragma unroll 4
    for (int k = 0; k < H_; k++) acc = fmaf(ln[k], W1[k * P_ + tid], acc);
    // exact GELU (matches torch nn.GELU default / jax approximate=False)
    out[tid] = 0.5f * acc * (1.0f + erff(acc * 0.70710678118654752f));
}

// ============================================================
// K4: GEMV(P->P) + l2norm, one block per row
// grid = 2*B_ blocks, 384 threads
// ============================================================
__global__ void k_proj2(const float* __restrict__ W2e, const float* __restrict__ b2e,
                        const float* __restrict__ W2t, const float* __restrict__ b2t) {
    const int bid  = blockIdx.x;
    const bool is_e = bid < B_;
    const float* W2 = is_e ? W2e : W2t;
    const float* b2 = is_e ? b2e : b2t;
    const float* h  = g_h1 + bid * P_;
    float* z = g_z + bid * P_;

    __shared__ float hs[P_];
    __shared__ float red[P_];
    const int tid = threadIdx.x;
    hs[tid] = h[tid];
    __syncthreads();

    float acc = b2[tid];
    #pragma unroll 4
    for (int k = 0; k < P_; k++) acc = fmaf(hs[k], W2[k * P_ + tid], acc);

    float n2 = blockreduce384(acc * acc, red, tid);
    float nrm = fmaxf(sqrtf(n2), 1e-12f);
    z[tid] = acc / nrm;
}

// ============================================================
// K5: finisher — CE reduction, InfoNCE align, BoW BCE,
//     diversity, variance, weighted combine. 1 block, 256 thr.
// ============================================================
__global__ void k_final(const float* __restrict__ enc, const int* __restrict__ labels,
                        const float* __restrict__ Wb, const float* __restrict__ bb,
                        float* __restrict__ out) {
    const int tid = threadIdx.x;
    __shared__ float red[256];
    __shared__ float sim[B_ * B_];
    __shared__ float rowloss[B_], colloss[B_];
    __shared__ float norms[B_];
    __shared__ float acc_terms[6];   // [ce_num, ce_den, align, bce, div, var]

    // ---- CE reduction ----
    float a = 0.0f, w = 0.0f;
    for (int i = tid; i < BT_; i += 256) { a += g_ce[i]; w += g_vf[i]; }
    red[tid] = a; __syncthreads();
    for (int off = 128; off > 0; off >>= 1) { if (tid < off) red[tid] += red[tid + off]; __syncthreads(); }
    if (tid == 0) acc_terms[0] = red[0];
    __syncthreads();
    red[tid] = w; __syncthreads();
    for (int off = 128; off > 0; off >>= 1) { if (tid < off) red[tid] += red[tid + off]; __syncthreads(); }
    if (tid == 0) acc_terms[1] = red[0];
    __syncthreads();

    // ---- sim = (z_e @ z_t^T)/tau ----
    {
        int i = tid >> 4, j = tid & 15;
        const float* ze = g_z + i * P_;
        const float* zt = g_z + (B_ + j) * P_;
        float acc = 0.0f;
        #pragma unroll 4
        for (int k = 0; k < P_; k++) acc = fmaf(ze[k], zt[k], acc);
        sim[i * 16 + j] = acc / TAU_;
    }
    __syncthreads();
    if (tid < B_) {
        float mx = -1e30f;
        for (int j = 0; j < B_; j++) mx = fmaxf(mx, sim[tid * 16 + j]);
        float se = 0.0f;
        for (int j = 0; j < B_; j++) se += expf(sim[tid * 16 + j] - mx);
        rowloss[tid] = -(sim[tid * 16 + tid] - (mx + logf(se)));
        float mc = -1e30f;
        for (int i = 0; i < B_; i++) mc = fmaxf(mc, sim[i * 16 + tid]);
        float sc = 0.0f;
        for (int i = 0; i < B_; i++) sc += expf(sim[i * 16 + tid] - mc);
        colloss[tid] = -(sim[tid * 16 + tid] - (mc + logf(sc)));
    }
    __syncthreads();
    if (tid == 0) {
        float li = 0.0f, lj = 0.0f;
        for (int i = 0; i < B_; i++) { li += rowloss[i]; lj += colloss[i]; }
        acc_terms[2] = 0.5f * (li + lj) / (float)B_;
    }

    // ---- BoW BCE ----
    float bacc = 0.0f;
    for (int e = tid; e < B_ * NBOW_; e += 256) {
        int b = e / NBOW_, i = e % NBOW_;
        float bl = bb[i];
        const float* er = enc + b * H_;
        #pragma unroll 4
        for (int k = 0; k < H_; k++) bl = fmaf(er[k], Wb[k * NBOW_ + i], bl);
        int id = i * 500;
        bool tset = false;
        for (int t = 0; t < T_; t++) {
            int lab = labels[b * T_ + t];
            bool valid = (lab != 0) && (lab != -100);
            int lc = lab < 0 ? 0 : (lab >= V_ ? V_ - 1 : lab);
            tset = tset || (valid && lc == id);
        }
        float tt = tset ? 1.0f : 0.0f;
        bacc += fmaxf(bl, 0.0f) - bl * tt + log1pf(expf(-fabsf(bl)));
    }
    __syncthreads();
    red[tid] = bacc; __syncthreads();
    for (int off = 128; off > 0; off >>= 1) { if (tid < off) red[tid] += red[tid + off]; __syncthreads(); }
    if (tid == 0) acc_terms[3] = red[0] / (float)(B_ * NBOW_);
    __syncthreads();

    // ---- diversity ----
    if (tid < B_) {
        float n2 = 0.0f;
        for (int k = 0; k < H_; k++) { float v = enc[tid * H_ + k]; n2 += v * v; }
        norms[tid] = fmaxf(sqrtf(n2), 1e-12f);
    }
    __syncthreads();
    float dacc = 0.0f;
    {
        int i = tid >> 4, j = tid & 15;
        if (i != j) {
            float d = 0.0f;
            #pragma unroll 4
            for (int k = 0; k < H_; k++) d = fmaf(enc[i * H_ + k], enc[j * H_ + k], d);
            dacc = fabsf(d / (norms[i] * norms[j]));
        }
    }
    __syncthreads();
    red[tid] = dacc; __syncthreads();
    for (int off = 128; off > 0; off >>= 1) { if (tid < off) red[tid] += red[tid + off]; __syncthreads(); }
    if (tid == 0) acc_terms[4] = red[0] / (float)(B_ * B_ - B_);
    __syncthreads();

    // ---- variance (ddof=1) ----
    float vacc = 0.0f;
    for (int k = tid; k < H_; k += 256) {
        float mu = 0.0f;
        for (int b = 0; b < B_; b++) mu += enc[b * H_ + k];
        mu *= (1.0f / (float)B_);
        float ss = 0.0f;
        for (int b = 0; b < B_; b++) { float d = enc[b * H_ + k] - mu; ss += d * d; }
        vacc += expf(-(ss / (float)(B_ - 1)));
    }
    __syncthreads();
    red[tid] = vacc; __syncthreads();
    for (int off = 128; off > 0; off >>= 1) { if (tid < off) red[tid] += red[tid + off]; __syncthreads(); }
    if (tid == 0) acc_terms[5] = red[0] / (float)H_;
    __syncthreads();

    if (tid == 0) {
        float ce = acc_terms[0] / fmaxf(acc_terms[1], 1.0f);
        out[0] = 1.0f * ce + 0.5f * acc_terms[2] + 0.2f * acc_terms[3]
               + 0.1f * acc_terms[4] + 0.05f * acc_terms[5];
    }
}

// ============================================================
extern "C" void kernel_launch(void* const* d_in, const int* in_sizes, int n_in,
                              void* d_out, int out_size) {
    const float* logits = (const float*)d_in[0];
    const int*   labels = (const int*)  d_in[1];
    const int*   amask  = (const int*)  d_in[2];
    const float* enc    = (const float*)d_in[3];
    const float* dec    = (const float*)d_in[4];
    const float* ln_g_e = (const float*)d_in[5];
    const float* ln_b_e = (const float*)d_in[6];
    const float* W1e    = (const float*)d_in[7];
    const float* b1e    = (const float*)d_in[8];
    const float* W2e    = (const float*)d_in[9];
    const float* b2e    = (const float*)d_in[10];
    const float* ln_g_t = (const float*)d_in[11];
    const float* ln_b_t = (const float*)d_in[12];
    const float* W1t    = (const float*)d_in[13];
    const float* b1t    = (const float*)d_in[14];
    const float* W2t    = (const float*)d_in[15];
    const float* b2t    = (const float*)d_in[16];
    const float* Wb     = (const float*)d_in[17];
    const float* bb     = (const float*)d_in[18];
    float* out = (float*)d_out;

    k_ce   <<<BT_,   256>>>(logits, labels);
    k_pool <<<B_,    256>>>(dec, amask);
    k_proj1<<<2*B_,  P_ >>>(enc, ln_g_e, ln_b_e, W1e, b1e, ln_g_t, ln_b_t, W1t, b1t);
    k_proj2<<<2*B_,  P_ >>>(W2e, b2e, W2t, b2t);
    k_final<<<1,     256>>>(enc, labels, Wb, bb, out);
}

// round 3
// speedup vs baseline: 3.3255x; 3.3255x over previous
#include <cuda_runtime.h>
#include <math.h>

#define B_    16
#define T_    128
#define V_    32000
#define H_    768
#define P_    384
#define NBOW_ 64
#define BT_   (B_ * T_)
#define EPS_  0.05f
#define TAU_  0.07f

// ---- scratch (__device__ globals; no allocation allowed) ----
__device__ float g_ce[BT_];
__device__ float g_vf[BT_];
__device__ float g_pooled[B_ * H_];
__device__ float g_h1[2 * B_ * P_];
__device__ float g_z [2 * B_ * P_];
__device__ float g_gram[B_ * B_];   // enc @ enc^T (raw dots, incl diag)
__device__ float g_simm[B_ * B_];   // z_e @ z_t^T (raw dots)
__device__ float g_bce [B_];        // per-batch-row sum of 64 bce terms

// ============================================================
// K1: per-token label-smoothed CE partials (online logsumexp)
// grid = BT_, block = 256; dual accumulators for ILP
// ============================================================
__global__ void k_ce(const float* __restrict__ logits, const int* __restrict__ labels) {
    const int tok = blockIdx.x;
    const int tid = threadIdx.x;
    const float4* p = reinterpret_cast<const float4*>(logits + (size_t)tok * V_);

    float m0 = -1e30f, s0 = 0.0f, t0 = 0.0f;
    float m1 = -1e30f, s1 = 0.0f, t1 = 0.0f;
    for (int i = tid; i < V_ / 4; i += 256) {
        float4 v = p[i];
        t0 += v.x; t1 += v.y;
        if (v.x > m0) { s0 = s0 * __expf(m0 - v.x) + 1.0f; m0 = v.x; } else s0 += __expf(v.x - m0);
        if (v.y > m1) { s1 = s1 * __expf(m1 - v.y) + 1.0f; m1 = v.y; } else s1 += __expf(v.y - m1);
        t0 += v.z; t1 += v.w;
        if (v.z > m0) { s0 = s0 * __expf(m0 - v.z) + 1.0f; m0 = v.z; } else s0 += __expf(v.z - m0);
        if (v.w > m1) { s1 = s1 * __expf(m1 - v.w) + 1.0f; m1 = v.w; } else s1 += __expf(v.w - m1);
    }
    // merge dual accumulators
    float M = fmaxf(m0, m1);
    float S = s0 * __expf(m0 - M) + s1 * __expf(m1 - M);
    float TS = t0 + t1;

    __shared__ float shm[256], shs[256], sht[256];
    shm[tid] = M; shs[tid] = S; sht[tid] = TS;
    __syncthreads();
    for (int off = 128; off > 0; off >>= 1) {
        if (tid < off) {
            float m2 = shm[tid + off], s2 = shs[tid + off];
            float MM = fmaxf(shm[tid], m2);
            shs[tid] = shs[tid] * __expf(shm[tid] - MM) + s2 * __expf(m2 - MM);
            shm[tid] = MM;
            sht[tid] += sht[tid + off];
        }
        __syncthreads();
    }

    if (tid == 0) {
        float lse = shm[0] + logf(shs[0]);
        int lab = labels[tok];
        bool valid = (lab != 0) && (lab != -100);
        int lc = lab < 0 ? 0 : (lab >= V_ ? V_ - 1 : lab);
        float xl = logits[(size_t)tok * V_ + lc];
        float lp_lab = xl - lse;
        float lp_sum = sht[0] - (float)V_ * lse;
        float loss = -((1.0f - EPS_) * lp_lab + (EPS_ / (float)V_) * lp_sum);
        g_ce[tok] = valid ? loss : 0.0f;
        g_vf[tok] = valid ? 1.0f : 0.0f;
    }
}

// ============================================================
// K2: masked mean-pool. grid = B_, block = 768 (one thread per h)
// ============================================================
__global__ void k_pool(const float* __restrict__ dec, const int* __restrict__ mask) {
    const int b = blockIdx.x;
    const int tid = threadIdx.x;
    __shared__ float shm[128];
    if (tid < 128) shm[tid] = (float)mask[b * T_ + tid];
    __syncthreads();
    if (tid < 64) shm[tid] += shm[tid + 64];
    __syncthreads();
    if (tid < 32) {
        float v = shm[tid] + shm[tid + 32];
        #pragma unroll
        for (int off = 16; off > 0; off >>= 1) v += __shfl_down_sync(0xffffffffu, v, off);
        if (tid == 0) shm[0] = fmaxf(v, 1.0f);
    }
    __syncthreads();
    float inv = 1.0f / shm[0];

    float a0 = 0.f, a1 = 0.f, a2 = 0.f, a3 = 0.f;
    const float* base = dec + (size_t)b * T_ * H_ + tid;
    #pragma unroll 4
    for (int t = 0; t < T_; t += 4) {
        float mk0 = (float)mask[b * T_ + t + 0];
        float mk1 = (float)mask[b * T_ + t + 1];
        float mk2 = (float)mask[b * T_ + t + 2];
        float mk3 = (float)mask[b * T_ + t + 3];
        a0 = fmaf(base[(size_t)(t + 0) * H_], mk0, a0);
        a1 = fmaf(base[(size_t)(t + 1) * H_], mk1, a1);
        a2 = fmaf(base[(size_t)(t + 2) * H_], mk2, a2);
        a3 = fmaf(base[(size_t)(t + 3) * H_], mk3, a3);
    }
    g_pooled[b * H_ + tid] = (a0 + a1 + a2 + a3) * inv;
}

// ---- 384-thread block sum: fold 384->256 then pow2 tree ----
__device__ __forceinline__ float blockreduce384(float v, float* red, int tid) {
    red[tid] = v;
    __syncthreads();
    if (tid < 128) red[tid] += red[tid + 256];
    __syncthreads();
    for (int off = 128; off > 0; off >>= 1) {
        if (tid < off) red[tid] += red[tid + off];
        __syncthreads();
    }
    float r = red[0];
    __syncthreads();
    return r;
}

// ============================================================
// K3: LN + GEMV(768->384) + exact GELU. grid = 2*B_, block = 384
// ============================================================
__global__ void k_proj1(const float* __restrict__ enc,
                        const float* __restrict__ g_e, const float* __restrict__ be_,
                        const float* __restrict__ W1e, const float* __restrict__ b1e,
                        const float* __restrict__ g_t, const float* __restrict__ bt_,
                        const float* __restrict__ W1t, const float* __restrict__ b1t) {
    const int bid  = blockIdx.x;
    const bool is_e = bid < B_;
    const int row  = is_e ? bid : bid - B_;
    const float* x  = is_e ? (enc + row * H_) : (g_pooled + row * H_);
    const float* g  = is_e ? g_e : g_t;
    const float* bn = is_e ? be_ : bt_;
    const float* W1 = is_e ? W1e : W1t;
    const float* b1 = is_e ? b1e : b1t;
    float* out = g_h1 + bid * P_;

    __shared__ float ln[H_];
    __shared__ float red[P_];
    const int tid = threadIdx.x;

    float a0 = x[tid], a1 = x[tid + P_];
    float mean = blockreduce384(a0 + a1, red, tid) * (1.0f / (float)H_);
    float d0 = a0 - mean, d1 = a1 - mean;
    float var = blockreduce384(d0 * d0 + d1 * d1, red, tid) * (1.0f / (float)H_);
    float inv = rsqrtf(var + 1e-5f);

    ln[tid]      = d0 * inv * g[tid]      + bn[tid];
    ln[tid + P_] = d1 * inv * g[tid + P_] + bn[tid + P_];
    __syncthreads();

    float acc = b1[tid];
    #pragma unroll 16
    for (int k = 0; k < H_; k++) acc = fmaf(ln[k], W1[k * P_ + tid], acc);
    out[tid] = 0.5f * acc * (1.0f + erff(acc * 0.70710678118654752f));
}

// ============================================================
// K4: GEMV(384->384) + l2norm. grid = 2*B_, block = 384
// ============================================================
__global__ void k_proj2(const float* __restrict__ W2e, const float* __restrict__ b2e,
                        const float* __restrict__ W2t, const float* __restrict__ b2t) {
    const int bid  = blockIdx.x;
    const bool is_e = bid < B_;
    const float* W2 = is_e ? W2e : W2t;
    const float* b2 = is_e ? b2e : b2t;
    const float* h  = g_h1 + bid * P_;
    float* z = g_z + bid * P_;

    __shared__ float hs[P_];
    __shared__ float red[P_];
    const int tid = threadIdx.x;
    hs[tid] = h[tid];
    __syncthreads();

    float acc = b2[tid];
    #pragma unroll 16
    for (int k = 0; k < P_; k++) acc = fmaf(hs[k], W2[k * P_ + tid], acc);

    float n2 = blockreduce384(acc * acc, red, tid);
    float nrm = fmaxf(sqrtf(n2), 1e-12f);
    z[tid] = acc / nrm;
}

// ---- 128-thread split-dot reduce (4 warps) ----
__device__ __forceinline__ float blockdot128(float v, int tid) {
    #pragma unroll
    for (int off = 16; off > 0; off >>= 1) v += __shfl_down_sync(0xffffffffu, v, off);
    __shared__ float w[4];
    if ((tid & 31) == 0) w[tid >> 5] = v;
    __syncthreads();
    return w[0] + w[1] + w[2] + w[3];
}

// ============================================================
// K5: Gram matrix of encoder_features (256 blocks) — for diversity
// ============================================================
__global__ void k_gram(const float* __restrict__ enc) {
    const int i = blockIdx.x >> 4, j = blockIdx.x & 15;
    const int tid = threadIdx.x;
    float acc = 0.0f;
    const float* a = enc + i * H_;
    const float* b = enc + j * H_;
    #pragma unroll
    for (int k = tid; k < H_; k += 128) acc = fmaf(a[k], b[k], acc);
    float d = blockdot128(acc, tid);
    if (tid == 0) g_gram[blockIdx.x] = d;
}

// ============================================================
// K6: sim matrix z_e @ z_t^T (256 blocks)
// ============================================================
__global__ void k_sim() {
    const int i = blockIdx.x >> 4, j = blockIdx.x & 15;
    const int tid = threadIdx.x;
    const float* a = g_z + i * P_;
    const float* b = g_z + (B_ + j) * P_;
    float acc = 0.0f;
    #pragma unroll
    for (int k = tid; k < P_; k += 128) acc = fmaf(a[k], b[k], acc);
    float d = blockdot128(acc, tid);
    if (tid == 0) g_simm[blockIdx.x] = d;
}

// ============================================================
// K7: BoW BCE per batch row. grid = B_, block = 128
// tid%64 = bow index i, tid/64 = k-half
// ============================================================
__global__ void k_bow(const float* __restrict__ enc, const int* __restrict__ labels,
                      const float* __restrict__ Wb, const float* __restrict__ bb) {
    const int b = blockIdx.x;
    const int tid = threadIdx.x;
    const int i = tid & 63, half = tid >> 6;

    __shared__ int bow_hit[NBOW_];
    __shared__ float part[128];
    __shared__ float term[NBOW_];
    if (tid < NBOW_) bow_hit[tid] = 0;
    __syncthreads();
    {
        int lab = labels[b * T_ + tid];              // tid < 128 == T_
        bool valid = (lab != 0) && (lab != -100);
        int lc = lab < 0 ? 0 : (lab >= V_ ? V_ - 1 : lab);
        if (valid && (lc % 500 == 0)) {
            int q = lc / 500;
            if (q < NBOW_) bow_hit[q] = 1;
        }
    }
    __syncthreads();

    const float* er = enc + b * H_;
    float acc = 0.0f;
    const int k0 = half * (H_ / 2);
    #pragma unroll 16
    for (int k = 0; k < H_ / 2; k++)
        acc = fmaf(er[k0 + k], Wb[(k0 + k) * NBOW_ + i], acc);
    part[tid] = acc;
    __syncthreads();

    if (tid < NBOW_) {
        float bl = bb[tid] + part[tid] + part[tid + 64];
        float tt = (float)bow_hit[tid];
        term[tid] = fmaxf(bl, 0.0f) - bl * tt + log1pf(expf(-fabsf(bl)));
    }
    __syncthreads();
    if (tid < 32) {
        float v = term[tid] + term[tid + 32];
        #pragma unroll
        for (int off = 16; off > 0; off >>= 1) v += __shfl_down_sync(0xffffffffu, v, off);
        if (tid == 0) g_bce[b] = v;
    }
}

// ============================================================
// K8: finisher — combine all terms. 1 block, 256 threads.
// ============================================================
__global__ void k_final(const float* __restrict__ enc, float* __restrict__ out) {
    const int tid = threadIdx.x;
    __shared__ float red[256];
    __shared__ float rowloss[B_], colloss[B_];
    __shared__ float acc_terms[6];   // [ce_num, ce_den, align, bce, div, var]

    // ---- CE reduction ----
    float a = 0.0f, w = 0.0f;
    #pragma unroll
    for (int i = tid; i < BT_; i += 256) { a += g_ce[i]; w += g_vf[i]; }
    red[tid] = a; __syncthreads();
    for (int off = 128; off > 0; off >>= 1) { if (tid < off) red[tid] += red[tid + off]; __syncthreads(); }
    if (tid == 0) acc_terms[0] = red[0];
    __syncthreads();
    red[tid] = w; __syncthreads();
    for (int off = 128; off > 0; off >>= 1) { if (tid < off) red[tid] += red[tid + off]; __syncthreads(); }
    if (tid == 0) acc_terms[1] = red[0];
    __syncthreads();

    // ---- align from g_simm ----
    if (tid < B_) {
        float srow[B_], scol[B_];
        #pragma unroll
        for (int j = 0; j < B_; j++) { srow[j] = g_simm[tid * 16 + j] / TAU_; scol[j] = g_simm[j * 16 + tid] / TAU_; }
        float mx = -1e30f, mc = -1e30f;
        #pragma unroll
        for (int j = 0; j < B_; j++) { mx = fmaxf(mx, srow[j]); mc = fmaxf(mc, scol[j]); }
        float se = 0.f, sc = 0.f;
        #pragma unroll
        for (int j = 0; j < B_; j++) { se += expf(srow[j] - mx); sc += expf(scol[j] - mc); }
        rowloss[tid] = -(srow[tid] - (mx + logf(se)));
        colloss[tid] = -(scol[tid] - (mc + logf(sc)));
    }
    __syncthreads();
    if (tid == 0) {
        float li = 0.f, lj = 0.f;
        #pragma unroll
        for (int i = 0; i < B_; i++) { li += rowloss[i]; lj += colloss[i]; }
        acc_terms[2] = 0.5f * (li + lj) / (float)B_;
        float bs = 0.f;
        #pragma unroll
        for (int i = 0; i < B_; i++) bs += g_bce[i];
        acc_terms[3] = bs / (float)(B_ * NBOW_);
    }

    // ---- diversity from g_gram ----
    float dacc = 0.0f;
    {
        int i = tid >> 4, j = tid & 15;
        if (i != j) {
            float ni = fmaxf(sqrtf(g_gram[i * 16 + i]), 1e-12f);
            float nj = fmaxf(sqrtf(g_gram[j * 16 + j]), 1e-12f);
            dacc = fabsf(g_gram[i * 16 + j] / (ni * nj));
        }
    }
    __syncthreads();
    red[tid] = dacc; __syncthreads();
    for (int off = 128; off > 0; off >>= 1) { if (tid < off) red[tid] += red[tid + off]; __syncthreads(); }
    if (tid == 0) acc_terms[4] = red[0] / (float)(B_ * B_ - B_);
    __syncthreads();

    // ---- variance (ddof=1) over enc columns ----
    float vacc = 0.0f;
    #pragma unroll
    for (int c = 0; c < 3; c++) {
        int k = tid + c * 256;
        float mu = 0.0f;
        #pragma unroll
        for (int b = 0; b < B_; b++) mu += enc[b * H_ + k];
        mu *= (1.0f / (float)B_);
        float ss = 0.0f;
        #pragma unroll
        for (int b = 0; b < B_; b++) { float d = enc[b * H_ + k] - mu; ss += d * d; }
        vacc += expf(-(ss * (1.0f / (float)(B_ - 1))));
    }
    __syncthreads();
    red[tid] = vacc; __syncthreads();
    for (int off = 128; off > 0; off >>= 1) { if (tid < off) red[tid] += red[tid + off]; __syncthreads(); }
    if (tid == 0) acc_terms[5] = red[0] / (float)H_;
    __syncthreads();

    if (tid == 0) {
        float ce = acc_terms[0] / fmaxf(acc_terms[1], 1.0f);
        out[0] = 1.0f * ce + 0.5f * acc_terms[2] + 0.2f * acc_terms[3]
               + 0.1f * acc_terms[4] + 0.05f * acc_terms[5];
    }
}

// ============================================================
extern "C" void kernel_launch(void* const* d_in, const int* in_sizes, int n_in,
                              void* d_out, int out_size) {
    const float* logits = (const float*)d_in[0];
    const int*   labels = (const int*)  d_in[1];
    const int*   amask  = (const int*)  d_in[2];
    const float* enc    = (const float*)d_in[3];
    const float* dec    = (const float*)d_in[4];
    const float* ln_g_e = (const float*)d_in[5];
    const float* ln_b_e = (const float*)d_in[6];
    const float* W1e    = (const float*)d_in[7];
    const float* b1e    = (const float*)d_in[8];
    const float* W2e    = (const float*)d_in[9];
    const float* b2e    = (const float*)d_in[10];
    const float* ln_g_t = (const float*)d_in[11];
    const float* ln_b_t = (const float*)d_in[12];
    const float* W1t    = (const float*)d_in[13];
    const float* b1t    = (const float*)d_in[14];
    const float* W2t    = (const float*)d_in[15];
    const float* b2t    = (const float*)d_in[16];
    const float* Wb     = (const float*)d_in[17];
    const float* bb     = (const float*)d_in[18];
    float* out = (float*)d_out;

    k_ce   <<<BT_,  256>>>(logits, labels);
    k_pool <<<B_,   H_ >>>(dec, amask);
    k_gram <<<256,  128>>>(enc);
    k_bow  <<<B_,   128>>>(enc, labels, Wb, bb);
    k_proj1<<<2*B_, P_ >>>(enc, ln_g_e, ln_b_e, W1e, b1e, ln_g_t, ln_b_t, W1t, b1t);
    k_proj2<<<2*B_, P_ >>>(W2e, b2e, W2t, b2t);
    k_sim  <<<256,  128>>>();
    k_final<<<1,    256>>>(enc, out);
}

// round 4
// speedup vs baseline: 4.4776x; 1.3464x over previous
#include <cuda_runtime.h>
#include <math.h>

#define B_    16
#define T_    128
#define V_    32000
#define H_    768
#define P_    384
#define NBOW_ 64
#define BT_   (B_ * T_)
#define EPS_  0.05f
#define TAU_  0.07f
#define CSH_  16.0f                      // logsumexp fixed shift
#define L2E_  1.4426950408889634f

// ---- scratch (__device__ globals; no allocation allowed) ----
__device__ float g_ce[BT_];
__device__ float g_vf[BT_];
__device__ float g_pooled[B_ * H_];
__device__ float g_h1[2 * B_ * P_];
__device__ float g_z [2 * B_ * P_];
__device__ float g_gram[B_ * B_];
__device__ float g_simm[B_ * B_];
__device__ float g_bce [B_];

// ============================================================
// K1: label-smoothed CE partials. Branchless fixed-shift LSE:
//     lse = C + log(sum exp(x - C)).  grid=BT_, block=256.
// ============================================================
__global__ void k_ce(const float* __restrict__ logits, const int* __restrict__ labels) {
    const int tok = blockIdx.x;
    const int tid = threadIdx.x;
    const float4* p = reinterpret_cast<const float4*>(logits + (size_t)tok * V_);

    float s0 = 0.f, s1 = 0.f, s2 = 0.f, s3 = 0.f;
    float t0 = 0.f, t1 = 0.f, t2 = 0.f, t3 = 0.f;
    for (int i = tid; i < V_ / 4; i += 256) {
        float4 v = p[i];
        t0 += v.x; t1 += v.y; t2 += v.z; t3 += v.w;
        s0 += __expf(v.x - CSH_);
        s1 += __expf(v.y - CSH_);
        s2 += __expf(v.z - CSH_);
        s3 += __expf(v.w - CSH_);
    }
    float S = (s0 + s1) + (s2 + s3);
    float TS = (t0 + t1) + (t2 + t3);

    __shared__ float shs[256], sht[256];
    shs[tid] = S; sht[tid] = TS;
    __syncthreads();
    for (int off = 128; off > 0; off >>= 1) {
        if (tid < off) { shs[tid] += shs[tid + off]; sht[tid] += sht[tid + off]; }
        __syncthreads();
    }

    if (tid == 0) {
        float lse = CSH_ + logf(shs[0]);
        int lab = labels[tok];
        bool valid = (lab != 0) && (lab != -100);
        int lc = lab < 0 ? 0 : (lab >= V_ ? V_ - 1 : lab);
        float xl = logits[(size_t)tok * V_ + lc];
        float lp_lab = xl - lse;
        float lp_sum = sht[0] - (float)V_ * lse;
        float loss = -((1.0f - EPS_) * lp_lab + (EPS_ / (float)V_) * lp_sum);
        g_ce[tok] = valid ? loss : 0.0f;
        g_vf[tok] = valid ? 1.0f : 0.0f;
    }
}

// ============================================================
// K2: masked mean-pool. grid=B_, block=768. 8 accumulators.
// ============================================================
__global__ void k_pool(const float* __restrict__ dec, const int* __restrict__ mask) {
    const int b = blockIdx.x;
    const int tid = threadIdx.x;
    __shared__ float mk[T_];
    __shared__ float minv;
    if (tid < T_) mk[tid] = (float)mask[b * T_ + tid];
    __syncthreads();
    if (tid == 0) {
        float s = 0.f;
        #pragma unroll
        for (int t = 0; t < T_; t++) s += mk[t];
        minv = 1.0f / fmaxf(s, 1.0f);
    }
    __syncthreads();

    const float* base = dec + (size_t)b * T_ * H_ + tid;
    float acc[8] = {0.f, 0.f, 0.f, 0.f, 0.f, 0.f, 0.f, 0.f};
    #pragma unroll
    for (int t = 0; t < T_; t += 8) {
        #pragma unroll
        for (int u = 0; u < 8; u++)
            acc[u] = fmaf(base[(size_t)(t + u) * H_], mk[t + u], acc[u]);
    }
    float r = ((acc[0] + acc[1]) + (acc[2] + acc[3])) + ((acc[4] + acc[5]) + (acc[6] + acc[7]));
    g_pooled[b * H_ + tid] = r * minv;
}

// ---- 384-thread block sum ----
__device__ __forceinline__ float blockreduce384(float v, float* red, int tid) {
    red[tid] = v;
    __syncthreads();
    if (tid < 128) red[tid] += red[tid + 256];
    __syncthreads();
    for (int off = 128; off > 0; off >>= 1) {
        if (tid < off) red[tid] += red[tid + off];
        __syncthreads();
    }
    float r = red[0];
    __syncthreads();
    return r;
}

// ============================================================
// K3: LN + GEMV(768->384) + exact GELU. grid=2*B_, block=384
// ============================================================
__global__ void k_proj1(const float* __restrict__ enc,
                        const float* __restrict__ g_e, const float* __restrict__ be_,
                        const float* __restrict__ W1e, const float* __restrict__ b1e,
                        const float* __restrict__ g_t, const float* __restrict__ bt_,
                        const float* __restrict__ W1t, const float* __restrict__ b1t) {
    const int bid  = blockIdx.x;
    const bool is_e = bid < B_;
    const int row  = is_e ? bid : bid - B_;
    const float* x  = is_e ? (enc + row * H_) : (g_pooled + row * H_);
    const float* g  = is_e ? g_e : g_t;
    const float* bn = is_e ? be_ : bt_;
    const float* W1 = is_e ? W1e : W1t;
    const float* b1 = is_e ? b1e : b1t;
    float* out = g_h1 + bid * P_;

    __shared__ float ln[H_];
    __shared__ float red[P_];
    const int tid = threadIdx.x;

    float a0 = x[tid], a1 = x[tid + P_];
    float mean = blockreduce384(a0 + a1, red, tid) * (1.0f / (float)H_);
    float d0 = a0 - mean, d1 = a1 - mean;
    float var = blockreduce384(d0 * d0 + d1 * d1, red, tid) * (1.0f / (float)H_);
    float inv = rsqrtf(var + 1e-5f);

    ln[tid]      = d0 * inv * g[tid]      + bn[tid];
    ln[tid + P_] = d1 * inv * g[tid + P_] + bn[tid + P_];
    __syncthreads();

    float acc = b1[tid];
    #pragma unroll 32
    for (int k = 0; k < H_; k++) acc = fmaf(ln[k], W1[k * P_ + tid], acc);
    out[tid] = 0.5f * acc * (1.0f + erff(acc * 0.70710678118654752f));
}

// ============================================================
// K4: GEMV(384->384) + l2norm. grid=2*B_, block=384
// ============================================================
__global__ void k_proj2(const float* __restrict__ W2e, const float* __restrict__ b2e,
                        const float* __restrict__ W2t, const float* __restrict__ b2t) {
    const int bid  = blockIdx.x;
    const bool is_e = bid < B_;
    const float* W2 = is_e ? W2e : W2t;
    const float* b2 = is_e ? b2e : b2t;
    const float* h  = g_h1 + bid * P_;
    float* z = g_z + bid * P_;

    __shared__ float hs[P_];
    __shared__ float red[P_];
    const int tid = threadIdx.x;
    hs[tid] = h[tid];
    __syncthreads();

    float acc = b2[tid];
    #pragma unroll 32
    for (int k = 0; k < P_; k++) acc = fmaf(hs[k], W2[k * P_ + tid], acc);

    float n2 = blockreduce384(acc * acc, red, tid);
    float nrm = fmaxf(sqrtf(n2), 1e-12f);
    z[tid] = acc / nrm;
}

// ---- 128-thread split-dot reduce ----
__device__ __forceinline__ float blockdot128(float v, int tid) {
    #pragma unroll
    for (int off = 16; off > 0; off >>= 1) v += __shfl_down_sync(0xffffffffu, v, off);
    __shared__ float w[4];
    if ((tid & 31) == 0) w[tid >> 5] = v;
    __syncthreads();
    return w[0] + w[1] + w[2] + w[3];
}

// ============================================================
// K5: Gram matrix of enc (256 blocks, 128 thr)
// ============================================================
__global__ void k_gram(const float* __restrict__ enc) {
    const int i = blockIdx.x >> 4, j = blockIdx.x & 15;
    const int tid = threadIdx.x;
    const float* a = enc + i * H_;
    const float* b = enc + j * H_;
    float acc = 0.0f;
    #pragma unroll
    for (int k = tid; k < H_; k += 128) acc = fmaf(a[k], b[k], acc);
    float d = blockdot128(acc, tid);
    if (tid == 0) g_gram[blockIdx.x] = d;
}

// ============================================================
// K6: sim matrix z_e @ z_t^T (256 blocks, 128 thr)
// ============================================================
__global__ void k_sim() {
    const int i = blockIdx.x >> 4, j = blockIdx.x & 15;
    const int tid = threadIdx.x;
    const float* a = g_z + i * P_;
    const float* b = g_z + (B_ + j) * P_;
    float acc = 0.0f;
    #pragma unroll
    for (int k = tid; k < P_; k += 128) acc = fmaf(a[k], b[k], acc);
    float d = blockdot128(acc, tid);
    if (tid == 0) g_simm[blockIdx.x] = d;
}

// ============================================================
// K7: BoW BCE. grid=B_, block=1024. split-k 16x (48 k each)
// ============================================================
__global__ void k_bow(const float* __restrict__ enc, const int* __restrict__ labels,
                      const float* __restrict__ Wb, const float* __restrict__ bb) {
    const int b = blockIdx.x;
    const int tid = threadIdx.x;
    const int i = tid & 63, c = tid >> 6;   // c in [0,16)

    __shared__ int bow_hit[NBOW_];
    __shared__ float part[1024];
    __shared__ float term[NBOW_];
    if (tid < NBOW_) bow_hit[tid] = 0;
    __syncthreads();
    if (tid < T_) {
        int lab = labels[b * T_ + tid];
        bool valid = (lab != 0) && (lab != -100);
        int lc = lab < 0 ? 0 : (lab >= V_ ? V_ - 1 : lab);
        if (valid && (lc % 500 == 0)) {
            int q = lc / 500;
            if (q < NBOW_) bow_hit[q] = 1;
        }
    }
    __syncthreads();

    const float* er = enc + b * H_;
    const int k0 = c * 48;
    float acc = 0.0f;
    #pragma unroll
    for (int k = 0; k < 48; k++)
        acc = fmaf(er[k0 + k], Wb[(k0 + k) * NBOW_ + i], acc);
    part[tid] = acc;
    __syncthreads();

    if (tid < NBOW_) {
        float bl = bb[tid];
        #pragma unroll
        for (int c2 = 0; c2 < 16; c2++) bl += part[c2 * 64 + tid];
        float tt = (float)bow_hit[tid];
        term[tid] = fmaxf(bl, 0.0f) - bl * tt + log1pf(expf(-fabsf(bl)));
    }
    __syncthreads();
    if (tid < 32) {
        float v = term[tid] + term[tid + 32];
        #pragma unroll
        for (int off = 16; off > 0; off >>= 1) v += __shfl_down_sync(0xffffffffu, v, off);
        if (tid == 0) g_bce[b] = v;
    }
}

// ============================================================
// K8: finisher. 1 block, 256 threads.
// ============================================================
__global__ void k_final(const float* __restrict__ enc, float* __restrict__ out) {
    const int tid = threadIdx.x;
    __shared__ float red[256];
    __shared__ float rowloss[B_], colloss[B_];
    __shared__ float acc_terms[6];

    // ---- CE reduction ----
    float a = 0.0f, w = 0.0f;
    #pragma unroll
    for (int i = 0; i < BT_ / 256; i++) { a += g_ce[tid + i * 256]; w += g_vf[tid + i * 256]; }
    red[tid] = a; __syncthreads();
    for (int off = 128; off > 0; off >>= 1) { if (tid < off) red[tid] += red[tid + off]; __syncthreads(); }
    if (tid == 0) acc_terms[0] = red[0];
    __syncthreads();
    red[tid] = w; __syncthreads();
    for (int off = 128; off > 0; off >>= 1) { if (tid < off) red[tid] += red[tid + off]; __syncthreads(); }
    if (tid == 0) acc_terms[1] = red[0];
    __syncthreads();

    // ---- align ----
    if (tid < B_) {
        float srow[B_], scol[B_];
        #pragma unroll
        for (int j = 0; j < B_; j++) { srow[j] = g_simm[tid * 16 + j] / TAU_; scol[j] = g_simm[j * 16 + tid] / TAU_; }
        float mx = -1e30f, mc = -1e30f;
        #pragma unroll
        for (int j = 0; j < B_; j++) { mx = fmaxf(mx, srow[j]); mc = fmaxf(mc, scol[j]); }
        float se = 0.f, sc = 0.f;
        #pragma unroll
        for (int j = 0; j < B_; j++) { se += expf(srow[j] - mx); sc += expf(scol[j] - mc); }
        rowloss[tid] = -(srow[tid] - (mx + logf(se)));
        colloss[tid] = -(scol[tid] - (mc + logf(sc)));
    }
    __syncthreads();
    if (tid == 0) {
        float li = 0.f, lj = 0.f;
        #pragma unroll
        for (int i = 0; i < B_; i++) { li += rowloss[i]; lj += colloss[i]; }
        acc_terms[2] = 0.5f * (li + lj) / (float)B_;
        float bs = 0.f;
        #pragma unroll
        for (int i = 0; i < B_; i++) bs += g_bce[i];
        acc_terms[3] = bs / (float)(B_ * NBOW_);
    }

    // ---- diversity ----
    float dacc = 0.0f;
    {
        int i = tid >> 4, j = tid & 15;
        if (i != j) {
            float ni = fmaxf(sqrtf(g_gram[i * 16 + i]), 1e-12f);
            float nj = fmaxf(sqrtf(g_gram[j * 16 + j]), 1e-12f);
            dacc = fabsf(g_gram[i * 16 + j] / (ni * nj));
        }
    }
    __syncthreads();
    red[tid] = dacc; __syncthreads();
    for (int off = 128; off > 0; off >>= 1) { if (tid < off) red[tid] += red[tid + off]; __syncthreads(); }
    if (tid == 0) acc_terms[4] = red[0] / (float)(B_ * B_ - B_);
    __syncthreads();

    // ---- variance (ddof=1) ----
    float vacc = 0.0f;
    #pragma unroll
    for (int c = 0; c < 3; c++) {
        int k = tid + c * 256;
        float mu = 0.0f;
        #pragma unroll
        for (int b = 0; b < B_; b++) mu += enc[b * H_ + k];
        mu *= (1.0f / (float)B_);
        float ss = 0.0f;
        #pragma unroll
        for (int b = 0; b < B_; b++) { float d = enc[b * H_ + k] - mu; ss += d * d; }
        vacc += expf(-(ss * (1.0f / (float)(B_ - 1))));
    }
    __syncthreads();
    red[tid] = vacc; __syncthreads();
    for (int off = 128; off > 0; off >>= 1) { if (tid < off) red[tid] += red[tid + off]; __syncthreads(); }
    if (tid == 0) acc_terms[5] = red[0] / (float)H_;
    __syncthreads();

    if (tid == 0) {
        float ce = acc_terms[0] / fmaxf(acc_terms[1], 1.0f);
        out[0] = 1.0f * ce + 0.5f * acc_terms[2] + 0.2f * acc_terms[3]
               + 0.1f * acc_terms[4] + 0.05f * acc_terms[5];
    }
}

// ============================================================
extern "C" void kernel_launch(void* const* d_in, const int* in_sizes, int n_in,
                              void* d_out, int out_size) {
    const float* logits = (const float*)d_in[0];
    const int*   labels = (const int*)  d_in[1];
    const int*   amask  = (const int*)  d_in[2];
    const float* enc    = (const float*)d_in[3];
    const float* dec    = (const float*)d_in[4];
    const float* ln_g_e = (const float*)d_in[5];
    const float* ln_b_e = (const float*)d_in[6];
    const float* W1e    = (const float*)d_in[7];
    const float* b1e    = (const float*)d_in[8];
    const float* W2e    = (const float*)d_in[9];
    const float* b2e    = (const float*)d_in[10];
    const float* ln_g_t = (const float*)d_in[11];
    const float* ln_b_t = (const float*)d_in[12];
    const float* W1t    = (const float*)d_in[13];
    const float* b1t    = (const float*)d_in[14];
    const float* W2t    = (const float*)d_in[15];
    const float* b2t    = (const float*)d_in[16];
    const float* Wb     = (const float*)d_in[17];
    const float* bb     = (const float*)d_in[18];
    float* out = (float*)d_out;

    k_ce   <<<BT_,  256 >>>(logits, labels);
    k_pool <<<B_,   H_  >>>(dec, amask);
    k_gram <<<256,  128 >>>(enc);
    k_bow  <<<B_,   1024>>>(enc, labels, Wb, bb);
    k_proj1<<<2*B_, P_  >>>(enc, ln_g_e, ln_b_e, W1e, b1e, ln_g_t, ln_b_t, W1t, b1t);
    k_proj2<<<2*B_, P_  >>>(W2e, b2e, W2t, b2t);
    k_sim  <<<256,  128 >>>();
    k_final<<<1,    256 >>>(enc, out);
}

// round 5
// speedup vs baseline: 4.7119x; 1.0523x over previous
#include <cuda_runtime.h>
#include <math.h>

#define B_    16
#define T_    128
#define V_    32000
#define H_    768
#define P_    384
#define NBOW_ 64
#define BT_   (B_ * T_)
#define EPS_  0.05f
#define TAU_  0.07f
#define CSH_  16.0f                      // logsumexp fixed shift

// ---- scratch (__device__ globals; no allocation allowed) ----
__device__ float g_ce[BT_];
__device__ float g_vf[BT_];
__device__ float g_h1[2 * B_ * P_];
__device__ float g_z [2 * B_ * P_];
__device__ float g_gram[B_ * B_];
__device__ float g_simm[B_ * B_];
__device__ float g_bce [B_];

// ============================================================
// K1: label-smoothed CE partials, fixed-shift LSE. grid=BT_, 256 thr.
// ============================================================
__global__ void k_ce(const float* __restrict__ logits, const int* __restrict__ labels) {
    const int tok = blockIdx.x;
    const int tid = threadIdx.x;
    const float4* p = reinterpret_cast<const float4*>(logits + (size_t)tok * V_);

    float s0 = 0.f, s1 = 0.f, s2 = 0.f, s3 = 0.f;
    float t0 = 0.f, t1 = 0.f, t2 = 0.f, t3 = 0.f;
    #pragma unroll 4
    for (int i = tid; i < V_ / 4; i += 256) {
        float4 v = p[i];
        t0 += v.x; t1 += v.y; t2 += v.z; t3 += v.w;
        s0 += __expf(v.x - CSH_);
        s1 += __expf(v.y - CSH_);
        s2 += __expf(v.z - CSH_);
        s3 += __expf(v.w - CSH_);
    }
    float S = (s0 + s1) + (s2 + s3);
    float TS = (t0 + t1) + (t2 + t3);

    __shared__ float shs[256], sht[256];
    shs[tid] = S; sht[tid] = TS;
    __syncthreads();
    for (int off = 128; off > 0; off >>= 1) {
        if (tid < off) { shs[tid] += shs[tid + off]; sht[tid] += sht[tid + off]; }
        __syncthreads();
    }

    if (tid == 0) {
        float lse = CSH_ + logf(shs[0]);
        int lab = labels[tok];
        bool valid = (lab != 0) && (lab != -100);
        int lc = lab < 0 ? 0 : (lab >= V_ ? V_ - 1 : lab);
        float xl = logits[(size_t)tok * V_ + lc];
        float lp_lab = xl - lse;
        float lp_sum = sht[0] - (float)V_ * lse;
        float loss = -((1.0f - EPS_) * lp_lab + (EPS_ / (float)V_) * lp_sum);
        g_ce[tok] = valid ? loss : 0.0f;
        g_vf[tok] = valid ? 1.0f : 0.0f;
    }
}

// ---- 384-thread block sum ----
__device__ __forceinline__ float blockreduce384(float v, float* red, int tid) {
    red[tid] = v;
    __syncthreads();
    if (tid < 128) red[tid] += red[tid + 256];
    __syncthreads();
    for (int off = 128; off > 0; off >>= 1) {
        if (tid < off) red[tid] += red[tid + off];
        __syncthreads();
    }
    float r = red[0];
    __syncthreads();
    return r;
}

// ============================================================
// K3: [fused pool +] LN + GEMV(768->384) + exact GELU.
// grid = 2*B_ (first 16 enc rows, next 16 text rows), block = 384
// ============================================================
__global__ void k_proj1(const float* __restrict__ enc,
                        const float* __restrict__ dec, const int* __restrict__ mask,
                        const float* __restrict__ g_e, const float* __restrict__ be_,
                        const float* __restrict__ W1e, const float* __restrict__ b1e,
                        const float* __restrict__ g_t, const float* __restrict__ bt_,
                        const float* __restrict__ W1t, const float* __restrict__ b1t) {
    const int bid  = blockIdx.x;
    const bool is_e = bid < B_;
    const int row  = is_e ? bid : bid - B_;
    const float* g  = is_e ? g_e : g_t;
    const float* bn = is_e ? be_ : bt_;
    const float* W1 = is_e ? W1e : W1t;
    const float* b1 = is_e ? b1e : b1t;
    float* out = g_h1 + bid * P_;

    __shared__ float ln[H_];
    __shared__ float red[P_];
    __shared__ float mk[T_];
    const int tid = threadIdx.x;

    float a0, a1;
    if (is_e) {
        a0 = enc[row * H_ + tid];
        a1 = enc[row * H_ + tid + P_];
    } else {
        // fused masked mean-pool for this text row
        if (tid < T_) mk[tid] = (float)mask[row * T_ + tid];
        __syncthreads();
        if (tid == 0) {
            float s = 0.f;
            #pragma unroll
            for (int t = 0; t < T_; t++) s += mk[t];
            red[0] = 1.0f / fmaxf(s, 1.0f);
        }
        __syncthreads();
        float minv = red[0];
        const float* base = dec + (size_t)row * T_ * H_ + tid;
        float p0 = 0.f, p1 = 0.f, q0 = 0.f, q1 = 0.f;
        #pragma unroll 8
        for (int t = 0; t < T_; t += 2) {
            p0 = fmaf(base[(size_t)t * H_],            mk[t],     p0);
            q0 = fmaf(base[(size_t)t * H_ + P_],       mk[t],     q0);
            p1 = fmaf(base[(size_t)(t + 1) * H_],      mk[t + 1], p1);
            q1 = fmaf(base[(size_t)(t + 1) * H_ + P_], mk[t + 1], q1);
        }
        a0 = (p0 + p1) * minv;
        a1 = (q0 + q1) * minv;
        __syncthreads();
    }

    float mean = blockreduce384(a0 + a1, red, tid) * (1.0f / (float)H_);
    float d0 = a0 - mean, d1 = a1 - mean;
    float var = blockreduce384(d0 * d0 + d1 * d1, red, tid) * (1.0f / (float)H_);
    float inv = rsqrtf(var + 1e-5f);

    ln[tid]      = d0 * inv * g[tid]      + bn[tid];
    ln[tid + P_] = d1 * inv * g[tid + P_] + bn[tid + P_];
    __syncthreads();

    float acc = b1[tid];
    #pragma unroll 32
    for (int k = 0; k < H_; k++) acc = fmaf(ln[k], W1[k * P_ + tid], acc);
    out[tid] = 0.5f * acc * (1.0f + erff(acc * 0.70710678118654752f));
}

// ============================================================
// K4: GEMV(384->384) + l2norm. grid=2*B_, block=384
// ============================================================
__global__ void k_proj2(const float* __restrict__ W2e, const float* __restrict__ b2e,
                        const float* __restrict__ W2t, const float* __restrict__ b2t) {
    const int bid  = blockIdx.x;
    const bool is_e = bid < B_;
    const float* W2 = is_e ? W2e : W2t;
    const float* b2 = is_e ? b2e : b2t;
    const float* h  = g_h1 + bid * P_;
    float* z = g_z + bid * P_;

    __shared__ float hs[P_];
    __shared__ float red[P_];
    const int tid = threadIdx.x;
    hs[tid] = h[tid];
    __syncthreads();

    float acc = b2[tid];
    #pragma unroll 32
    for (int k = 0; k < P_; k++) acc = fmaf(hs[k], W2[k * P_ + tid], acc);

    float n2 = blockreduce384(acc * acc, red, tid);
    float nrm = fmaxf(sqrtf(n2), 1e-12f);
    z[tid] = acc / nrm;
}

// ---- 128-thread split-dot reduce ----
__device__ __forceinline__ float blockdot128(float v, int tid) {
    #pragma unroll
    for (int off = 16; off > 0; off >>= 1) v += __shfl_down_sync(0xffffffffu, v, off);
    __shared__ float w[4];
    if ((tid & 31) == 0) w[tid >> 5] = v;
    __syncthreads();
    return w[0] + w[1] + w[2] + w[3];
}

// ============================================================
// K5: Gram matrix of enc (256 blocks, 128 thr)
// ============================================================
__global__ void k_gram(const float* __restrict__ enc) {
    const int i = blockIdx.x >> 4, j = blockIdx.x & 15;
    const int tid = threadIdx.x;
    const float* a = enc + i * H_;
    const float* b = enc + j * H_;
    float acc = 0.0f;
    #pragma unroll
    for (int k = tid; k < H_; k += 128) acc = fmaf(a[k], b[k], acc);
    float d = blockdot128(acc, tid);
    if (tid == 0) g_gram[blockIdx.x] = d;
}

// ============================================================
// K6: sim matrix z_e @ z_t^T (256 blocks, 128 thr)
// ============================================================
__global__ void k_sim() {
    const int i = blockIdx.x >> 4, j = blockIdx.x & 15;
    const int tid = threadIdx.x;
    const float* a = g_z + i * P_;
    const float* b = g_z + (B_ + j) * P_;
    float acc = 0.0f;
    #pragma unroll
    for (int k = tid; k < P_; k += 128) acc = fmaf(a[k], b[k], acc);
    float d = blockdot128(acc, tid);
    if (tid == 0) g_simm[blockIdx.x] = d;
}

// ============================================================
// K7: BoW BCE. grid=B_, block=1024. split-k 16x
// ============================================================
__global__ void k_bow(const float* __restrict__ enc, const int* __restrict__ labels,
                      const float* __restrict__ Wb, const float* __restrict__ bb) {
    const int b = blockIdx.x;
    const int tid = threadIdx.x;
    const int i = tid & 63, c = tid >> 6;

    __shared__ int bow_hit[NBOW_];
    __shared__ float part[1024];
    __shared__ float term[NBOW_];
    if (tid < NBOW_) bow_hit[tid] = 0;
    __syncthreads();
    if (tid < T_) {
        int lab = labels[b * T_ + tid];
        bool valid = (lab != 0) && (lab != -100);
        int lc = lab < 0 ? 0 : (lab >= V_ ? V_ - 1 : lab);
        if (valid && (lc % 500 == 0)) {
            int q = lc / 500;
            if (q < NBOW_) bow_hit[q] = 1;
        }
    }
    __syncthreads();

    const float* er = enc + b * H_;
    const int k0 = c * 48;
    float acc = 0.0f;
    #pragma unroll
    for (int k = 0; k < 48; k++)
        acc = fmaf(er[k0 + k], Wb[(k0 + k) * NBOW_ + i], acc);
    part[tid] = acc;
    __syncthreads();

    if (tid < NBOW_) {
        float bl = bb[tid];
        #pragma unroll
        for (int c2 = 0; c2 < 16; c2++) bl += part[c2 * 64 + tid];
        float tt = (float)bow_hit[tid];
        term[tid] = fmaxf(bl, 0.0f) - bl * tt + log1pf(expf(-fabsf(bl)));
    }
    __syncthreads();
    if (tid < 32) {
        float v = term[tid] + term[tid + 32];
        #pragma unroll
        for (int off = 16; off > 0; off >>= 1) v += __shfl_down_sync(0xffffffffu, v, off);
        if (tid == 0) g_bce[b] = v;
    }
}

// ============================================================
// K8: finisher. 1 block, 256 threads.
// ============================================================
__global__ void k_final(const float* __restrict__ enc, float* __restrict__ out) {
    const int tid = threadIdx.x;
    __shared__ float red[256];
    __shared__ float rowloss[B_], colloss[B_];
    __shared__ float acc_terms[6];

    float a = 0.0f, w = 0.0f;
    #pragma unroll
    for (int i = 0; i < BT_ / 256; i++) { a += g_ce[tid + i * 256]; w += g_vf[tid + i * 256]; }
    red[tid] = a; __syncthreads();
    for (int off = 128; off > 0; off >>= 1) { if (tid < off) red[tid] += red[tid + off]; __syncthreads(); }
    if (tid == 0) acc_terms[0] = red[0];
    __syncthreads();
    red[tid] = w; __syncthreads();
    for (int off = 128; off > 0; off >>= 1) { if (tid < off) red[tid] += red[tid + off]; __syncthreads(); }
    if (tid == 0) acc_terms[1] = red[0];
    __syncthreads();

    if (tid < B_) {
        float srow[B_], scol[B_];
        #pragma unroll
        for (int j = 0; j < B_; j++) { srow[j] = g_simm[tid * 16 + j] / TAU_; scol[j] = g_simm[j * 16 + tid] / TAU_; }
        float mx = -1e30f, mc = -1e30f;
        #pragma unroll
        for (int j = 0; j < B_; j++) { mx = fmaxf(mx, srow[j]); mc = fmaxf(mc, scol[j]); }
        float se = 0.f, sc = 0.f;
        #pragma unroll
        for (int j = 0; j < B_; j++) { se += expf(srow[j] - mx); sc += expf(scol[j] - mc); }
        rowloss[tid] = -(srow[tid] - (mx + logf(se)));
        colloss[tid] = -(scol[tid] - (mc + logf(sc)));
    }
    __syncthreads();
    if (tid == 0) {
        float li = 0.f, lj = 0.f;
        #pragma unroll
        for (int i = 0; i < B_; i++) { li += rowloss[i]; lj += colloss[i]; }
        acc_terms[2] = 0.5f * (li + lj) / (float)B_;
        float bs = 0.f;
        #pragma unroll
        for (int i = 0; i < B_; i++) bs += g_bce[i];
        acc_terms[3] = bs / (float)(B_ * NBOW_);
    }

    float dacc = 0.0f;
    {
        int i = tid >> 4, j = tid & 15;
        if (i != j) {
            float ni = fmaxf(sqrtf(g_gram[i * 16 + i]), 1e-12f);
            float nj = fmaxf(sqrtf(g_gram[j * 16 + j]), 1e-12f);
            dacc = fabsf(g_gram[i * 16 + j] / (ni * nj));
        }
    }
    __syncthreads();
    red[tid] = dacc; __syncthreads();
    for (int off = 128; off > 0; off >>= 1) { if (tid < off) red[tid] += red[tid + off]; __syncthreads(); }
    if (tid == 0) acc_terms[4] = red[0] / (float)(B_ * B_ - B_);
    __syncthreads();

    float vacc = 0.0f;
    #pragma unroll
    for (int c = 0; c < 3; c++) {
        int k = tid + c * 256;
        float mu = 0.0f;
        #pragma unroll
        for (int b = 0; b < B_; b++) mu += enc[b * H_ + k];
        mu *= (1.0f / (float)B_);
        float ss = 0.0f;
        #pragma unroll
        for (int b = 0; b < B_; b++) { float d = enc[b * H_ + k] - mu; ss += d * d; }
        vacc += expf(-(ss * (1.0f / (float)(B_ - 1))));
    }
    __syncthreads();
    red[tid] = vacc; __syncthreads();
    for (int off = 128; off > 0; off >>= 1) { if (tid < off) red[tid] += red[tid + off]; __syncthreads(); }
    if (tid == 0) acc_terms[5] = red[0] / (float)H_;
    __syncthreads();

    if (tid == 0) {
        float ce = acc_terms[0] / fmaxf(acc_terms[1], 1.0f);
        out[0] = 1.0f * ce + 0.5f * acc_terms[2] + 0.2f * acc_terms[3]
               + 0.1f * acc_terms[4] + 0.05f * acc_terms[5];
    }
}

// ---- streams/events created once at load (host-side resources only) ----
struct SideStreams {
    cudaStream_t sA, sB;
    cudaEvent_t  eFork, eA, eB;
    SideStreams() {
        cudaStreamCreateWithFlags(&sA, cudaStreamNonBlocking);
        cudaStreamCreateWithFlags(&sB, cudaStreamNonBlocking);
        cudaEventCreateWithFlags(&eFork, cudaEventDisableTiming);
        cudaEventCreateWithFlags(&eA,    cudaEventDisableTiming);
        cudaEventCreateWithFlags(&eB,    cudaEventDisableTiming);
    }
};
static SideStreams g_ss;

// ============================================================
extern "C" void kernel_launch(void* const* d_in, const int* in_sizes, int n_in,
                              void* d_out, int out_size) {
    const float* logits = (const float*)d_in[0];
    const int*   labels = (const int*)  d_in[1];
    const int*   amask  = (const int*)  d_in[2];
    const float* enc    = (const float*)d_in[3];
    const float* dec    = (const float*)d_in[4];
    const float* ln_g_e = (const float*)d_in[5];
    const float* ln_b_e = (const float*)d_in[6];
    const float* W1e    = (const float*)d_in[7];
    const float* b1e    = (const float*)d_in[8];
    const float* W2e    = (const float*)d_in[9];
    const float* b2e    = (const float*)d_in[10];
    const float* ln_g_t = (const float*)d_in[11];
    const float* ln_b_t = (const float*)d_in[12];
    const float* W1t    = (const float*)d_in[13];
    const float* b1t    = (const float*)d_in[14];
    const float* W2t    = (const float*)d_in[15];
    const float* b2t    = (const float*)d_in[16];
    const float* Wb     = (const float*)d_in[17];
    const float* bb     = (const float*)d_in[18];
    float* out = (float*)d_out;

    // fork side streams off the (possibly capturing) origin stream
    cudaEventRecord(g_ss.eFork, 0);
    cudaStreamWaitEvent(g_ss.sA, g_ss.eFork, 0);
    cudaStreamWaitEvent(g_ss.sB, g_ss.eFork, 0);

    // big kernel on origin stream
    k_ce<<<BT_, 256>>>(logits, labels);

    // side chain A: proj1(+pool) -> proj2 -> sim
    k_proj1<<<2*B_, P_, 0, g_ss.sA>>>(enc, dec, amask,
                                      ln_g_e, ln_b_e, W1e, b1e,
                                      ln_g_t, ln_b_t, W1t, b1t);
    k_proj2<<<2*B_, P_, 0, g_ss.sA>>>(W2e, b2e, W2t, b2t);
    k_sim  <<<256,  128, 0, g_ss.sA>>>();
    cudaEventRecord(g_ss.eA, g_ss.sA);

    // side chain B: gram, bow
    k_gram<<<256, 128,  0, g_ss.sB>>>(enc);
    k_bow <<<B_,  1024, 0, g_ss.sB>>>(enc, labels, Wb, bb);
    cudaEventRecord(g_ss.eB, g_ss.sB);

    // join and finish on origin stream
    cudaStreamWaitEvent(0, g_ss.eA, 0);
    cudaStreamWaitEvent(0, g_ss.eB, 0);
    k_final<<<1, 256>>>(enc, out);
}